// round 10
// baseline (speedup 1.0000x reference)
#include <cuda_runtime.h>
#include <cuda_fp16.h>
#include <cstdint>

// GraphAttentionLayer: B=8, N=2048, Fin=Fout=256
//  K1: Wh = h @ W^T  (tf32 mma.sync, 128x256 blocks, single wave)
//  K2: per-row E1=exp(f1), F1=exp(.2 f1), EF=(exp(f2), exp(.2 f2))
//  K3: fp16 m16n8k16 attention, 128i x 256o, KJ=64 chunks (32 barriers),
//      cp.async rings (A dbuf, B depth-3, adj depth-2), gen -> sync -> mma
//      w_ij = adj ? (E2_j > 1/E1_i ? E1_i*E2_j : F1_i*F2_j) : 0  (exact leaky+exp)

#define NROW   2048
#define FDIM   256
#define NBATCH 8
#define NTOT   (NBATCH * NROW)

#define K1ST 36
#define KJ   64
#define NIT  (NROW / KJ)   // 32

// ---------------- scratch ----------------
__device__ float  g_Wh [NTOT * FDIM];
__device__ __half g_Whh[NTOT * FDIM];
__device__ float  g_E1[NTOT], g_F1[NTOT];
__device__ float2 g_EF[NTOT];

// ---------------- helpers ----------------
__device__ __forceinline__ uint32_t to_tf32(float x) {
    uint32_t r; asm("cvt.rna.tf32.f32 %0, %1;" : "=r"(r) : "f"(x)); return r;
}
__device__ __forceinline__ void mma_tf32(float* d, const uint32_t* a, const uint32_t* b) {
    asm volatile(
        "mma.sync.aligned.m16n8k8.row.col.f32.tf32.tf32.f32 "
        "{%0,%1,%2,%3}, {%4,%5,%6,%7}, {%8,%9}, {%0,%1,%2,%3};"
        : "+f"(d[0]), "+f"(d[1]), "+f"(d[2]), "+f"(d[3])
        : "r"(a[0]), "r"(a[1]), "r"(a[2]), "r"(a[3]), "r"(b[0]), "r"(b[1]));
}
__device__ __forceinline__ void mma_f16(float* d, const uint32_t* a, const uint32_t* b) {
    asm volatile(
        "mma.sync.aligned.m16n8k16.row.col.f32.f16.f16.f32 "
        "{%0,%1,%2,%3}, {%4,%5,%6,%7}, {%8,%9}, {%0,%1,%2,%3};"
        : "+f"(d[0]), "+f"(d[1]), "+f"(d[2]), "+f"(d[3])
        : "r"(a[0]), "r"(a[1]), "r"(a[2]), "r"(a[3]), "r"(b[0]), "r"(b[1]));
}
__device__ __forceinline__ void ldm_x4(uint32_t* r, const void* p) {
    uint32_t a = (uint32_t)__cvta_generic_to_shared(p);
    asm volatile("ldmatrix.sync.aligned.m8n8.x4.shared.b16 {%0,%1,%2,%3}, [%4];"
                 : "=r"(r[0]), "=r"(r[1]), "=r"(r[2]), "=r"(r[3]) : "r"(a));
}
__device__ __forceinline__ void ldm_x4_t(uint32_t* r, const void* p) {
    uint32_t a = (uint32_t)__cvta_generic_to_shared(p);
    asm volatile("ldmatrix.sync.aligned.m8n8.x4.trans.shared.b16 {%0,%1,%2,%3}, [%4];"
                 : "=r"(r[0]), "=r"(r[1]), "=r"(r[2]), "=r"(r[3]) : "r"(a));
}
__device__ __forceinline__ void cp_async16(void* dst, const void* src) {
    uint32_t d = (uint32_t)__cvta_generic_to_shared(dst);
    asm volatile("cp.async.cg.shared.global [%0], [%1], 16;" :: "r"(d), "l"(src));
}
#define CP_COMMIT() asm volatile("cp.async.commit_group;" ::: "memory")
#define CP_WAIT1()  asm volatile("cp.async.wait_group 1;" ::: "memory")

// =====================================================================
// Kernel 1: Wh = h @ W^T, tf32 mma, 128n x 256o blocks, 512 threads.
// =====================================================================
__global__ void __launch_bounds__(512, 1) wh_mma_kernel(
    const float* __restrict__ h, const float* __restrict__ W,
    float* __restrict__ Wh, __half* __restrict__ Whh)
{
    extern __shared__ uint32_t sm1[];
    uint32_t* sA = sm1;                      // [2][128][K1ST]
    uint32_t* sB = sm1 + 2 * 128 * K1ST;     // [2][256][K1ST]

    const int t = threadIdx.x, wid = t >> 5, lid = t & 31;
    const int n0 = blockIdx.x * 128;
    const int rh = t >> 2, sh = (t & 3) * 8;
    const int rw = t >> 1, sw = (t & 1) * 16;
    const int wi = wid & 3, wo = wid >> 2;
    const int g = lid >> 2, tig = lid & 3;

    const float* hp = h + (size_t)(n0 + rh) * FDIM + sh;
    const float* wp = W + (size_t)rw * FDIM + sw;

    float d[2][8][4];
#pragma unroll
    for (int mi = 0; mi < 2; mi++)
#pragma unroll
        for (int ni = 0; ni < 8; ni++)
#pragma unroll
            for (int q = 0; q < 4; q++) d[mi][ni][q] = 0.f;

    float4 hr[2], wr[4];

    auto ldg = [&](int it) {
        const int f0 = it * 32;
        hr[0] = *(const float4*)(hp + f0);
        hr[1] = *(const float4*)(hp + f0 + 4);
#pragma unroll
        for (int q = 0; q < 4; q++)
            wr[q] = *(const float4*)(wp + f0 + q * 4);
    };
    auto sts = [&](int bf) {
        uint32_t* ab = sA + bf * 128 * K1ST + rh * K1ST + sh;
        uint32_t* bb = sB + bf * 256 * K1ST + rw * K1ST + sw;
#pragma unroll
        for (int q = 0; q < 2; q++)
            *(uint4*)(ab + q * 4) = make_uint4(to_tf32(hr[q].x), to_tf32(hr[q].y),
                                               to_tf32(hr[q].z), to_tf32(hr[q].w));
#pragma unroll
        for (int q = 0; q < 4; q++)
            *(uint4*)(bb + q * 4) = make_uint4(to_tf32(wr[q].x), to_tf32(wr[q].y),
                                               to_tf32(wr[q].z), to_tf32(wr[q].w));
    };
    auto mma_phase = [&](int bf) {
        const uint32_t* A = sA + bf * 128 * K1ST;
        const uint32_t* B = sB + bf * 256 * K1ST;
#pragma unroll
        for (int ks = 0; ks < 4; ks++) {
            uint32_t af[2][4];
#pragma unroll
            for (int mi = 0; mi < 2; mi++) {
                const int row = wi * 32 + mi * 16 + g;
                const int kc  = ks * 8 + tig;
                af[mi][0] = A[row * K1ST + kc];
                af[mi][1] = A[(row + 8) * K1ST + kc];
                af[mi][2] = A[row * K1ST + kc + 4];
                af[mi][3] = A[(row + 8) * K1ST + kc + 4];
            }
            uint32_t bfr[8][2];
#pragma unroll
            for (int ni = 0; ni < 8; ni++) {
                const int col = wo * 64 + ni * 8 + g;
                const int kc  = ks * 8 + tig;
                bfr[ni][0] = B[col * K1ST + kc];
                bfr[ni][1] = B[col * K1ST + kc + 4];
            }
#pragma unroll
            for (int mi = 0; mi < 2; mi++)
#pragma unroll
                for (int ni = 0; ni < 8; ni++)
                    mma_tf32(d[mi][ni], af[mi], bfr[ni]);
        }
    };

    ldg(0); sts(0); __syncthreads();
    for (int it = 0; it < 8; it++) {
        if (it + 1 < 8) ldg(it + 1);
        mma_phase(it & 1);
        if (it + 1 < 8) sts((it + 1) & 1);
        __syncthreads();
    }

#pragma unroll
    for (int mi = 0; mi < 2; mi++) {
        const int r0 = wi * 32 + mi * 16 + g;
        const int r1 = r0 + 8;
        float*  o0p = Wh + (size_t)(n0 + r0) * FDIM + wo * 64 + tig * 2;
        float*  o1p = Wh + (size_t)(n0 + r1) * FDIM + wo * 64 + tig * 2;
        __half* h0p = Whh + (size_t)(n0 + r0) * FDIM + wo * 64 + tig * 2;
        __half* h1p = Whh + (size_t)(n0 + r1) * FDIM + wo * 64 + tig * 2;
#pragma unroll
        for (int ni = 0; ni < 8; ni++) {
            *(float2*)(o0p + ni * 8) = make_float2(d[mi][ni][0], d[mi][ni][1]);
            *(float2*)(o1p + ni * 8) = make_float2(d[mi][ni][2], d[mi][ni][3]);
            *(__half2*)(h0p + ni * 8) =
                __float22half2_rn(make_float2(d[mi][ni][0], d[mi][ni][1]));
            *(__half2*)(h1p + ni * 8) =
                __float22half2_rn(make_float2(d[mi][ni][2], d[mi][ni][3]));
        }
    }
}

// =====================================================================
// Kernel 2: per-row f1,f2 -> E1, F1, (E2,F2)
// =====================================================================
__global__ void __launch_bounds__(256) fvec_kernel(
    const float* __restrict__ Wh, const float* __restrict__ a,
    float* __restrict__ E1, float* __restrict__ F1, float2* __restrict__ EF)
{
    const int row  = blockIdx.x * 8 + (threadIdx.x >> 5);
    const int lane = threadIdx.x & 31;
    const float4* wr = (const float4*)(Wh + (size_t)row * FDIM);
    const float4* a1 = (const float4*)a;
    const float4* a2 = (const float4*)(a + FDIM);

    float4 x0 = wr[lane], x1 = wr[lane + 32];
    float4 p0 = a1[lane], p1 = a1[lane + 32];
    float4 q0 = a2[lane], q1 = a2[lane + 32];

    float s1 = x0.x * p0.x + x0.y * p0.y + x0.z * p0.z + x0.w * p0.w
             + x1.x * p1.x + x1.y * p1.y + x1.z * p1.z + x1.w * p1.w;
    float s2 = x0.x * q0.x + x0.y * q0.y + x0.z * q0.z + x0.w * q0.w
             + x1.x * q1.x + x1.y * q1.y + x1.z * q1.z + x1.w * q1.w;
#pragma unroll
    for (int o = 16; o; o >>= 1) {
        s1 += __shfl_xor_sync(0xFFFFFFFFu, s1, o);
        s2 += __shfl_xor_sync(0xFFFFFFFFu, s2, o);
    }
    if (lane == 0) {
        E1[row] = __expf(s1);
        F1[row] = __expf(0.2f * s1);
        EF[row] = make_float2(__expf(s2), __expf(0.2f * s2));
    }
}

// =====================================================================
// Kernel 3: fp16 mma attention, KJ=64.
// =====================================================================
#define AST3 72            // A row stride (halves): 64 + 8 pad
#define BST3 264           // B k-row stride (halves): 256 + 8 pad
// smem layout (bytes)
#define OFF_A   0          // A: 2 * 128 * 72 * 2       = 36864
#define OFF_B   36864      // B ring: 3 * 64 * 264 * 2  = 101376
#define OFF_ADJ 138240     // adj ring: 2 * 128 * 64 * 4 = 65536
#define OFF_EF  203776     // EF: 2048 * 8              = 16384
#define OFF_DN  220160     // den: 512 * 4              =  2048
#define SM3_SZ  222208
#define ADJ_SLOT 32768     // 128 rows * 256 B
#define B_SLOT   33792     // 64 rows * 528 B

__global__ void __launch_bounds__(512, 1) attn_f16_kernel(
    const int*  __restrict__ adj,
    const __half* __restrict__ Whh,
    const float* __restrict__ E1, const float* __restrict__ F1,
    const float2* __restrict__ EF,
    float* __restrict__ out)
{
    extern __shared__ char smc[];
    __half* smA = (__half*)(smc + OFF_A);
    __half* smB = (__half*)(smc + OFF_B);
    char*   smJ = smc + OFF_ADJ;
    float2* sEF = (float2*)(smc + OFF_EF);
    float*  den = (float*)(smc + OFF_DN);

    const int t = threadIdx.x, wid = t >> 5, lid = t & 31;
    const int bz = blockIdx.y, i0 = blockIdx.x * 128;
    const int r  = t >> 2, jq = (t & 3) * 16;     // gen: row r, 16 j's
    const int krow = t >> 3, kseg = (t & 7) * 64; // B staging: k-row, 64-byte seg
    const int wi = wid & 3, wo = wid >> 2;
    const int g  = lid >> 2, tig = lid & 3;

    // ---- stage (E2,F2) once ----
    {
        const float4* src = (const float4*)(EF + bz * NROW);
        float4* dst = (float4*)sEF;
        dst[t]       = src[t];
        dst[t + 512] = src[t + 512];
    }

    const int row_g = bz * NROW + i0 + r;
    const float E1r  = E1[row_g], F1r = F1[row_g];
    const float tinv = __frcp_rn(E1r);            // s>0  <=>  E2_j > 1/E1_i

    // cp.async sources: each thread copies exactly the adj ints it later reads
    const char* adj_src = (const char*)(adj + (size_t)row_g * NROW) + jq * 4;
    const char* whh_src = (const char*)(Whh + (size_t)(bz * NROW + krow) * FDIM) + kseg;

    auto stage = [&](int c) {
        {   // adj slot c&1: row r, bytes [jq*4, +64)
            char* dst = smJ + (c & 1) * ADJ_SLOT + r * 256 + jq * 4;
            const char* src = adj_src + (size_t)c * (KJ * 4);
#pragma unroll
            for (int q = 0; q < 4; q++) cp_async16(dst + q * 16, src + q * 16);
        }
        {   // B slot c%3: k-row krow, bytes [kseg, +64)
            char* dst = (char*)smB + (c % 3) * B_SLOT + krow * (BST3 * 2) + kseg;
            const char* src = whh_src + (size_t)c * (KJ * FDIM * 2);
#pragma unroll
            for (int q = 0; q < 4; q++) cp_async16(dst + q * 16, src + q * 16);
        }
    };

    float d[2][8][4];
#pragma unroll
    for (int mi = 0; mi < 2; mi++)
#pragma unroll
        for (int ni = 0; ni < 8; ni++)
#pragma unroll
            for (int q = 0; q < 4; q++) d[mi][ni][q] = 0.f;
    float dn = 0.f;

    // gen chunk c: 16 weights -> fp16, STS into A[c&1]
    auto gen_sts = [&](int c) {
        const int4* ap = (const int4*)(smJ + (c & 1) * ADJ_SLOT + r * 256 + jq * 4);
        const float4* ef4 = (const float4*)(sEF + c * KJ + jq);
        uint32_t pk[8];
#pragma unroll
        for (int q = 0; q < 4; q++) {
            const int4 am = ap[q];
            const float4 efa = ef4[q * 2];       // (E2,F2) j= qq*4+0,1
            const float4 efb = ef4[q * 2 + 1];   // j= qq*4+2,3
            float w0 = am.x ? (efa.x > tinv ? E1r * efa.x : F1r * efa.y) : 0.f;
            float w1 = am.y ? (efa.z > tinv ? E1r * efa.z : F1r * efa.w) : 0.f;
            float w2 = am.z ? (efb.x > tinv ? E1r * efb.x : F1r * efb.y) : 0.f;
            float w3 = am.w ? (efb.z > tinv ? E1r * efb.z : F1r * efb.w) : 0.f;
            dn += (w0 + w1) + (w2 + w3);
            __half2 p0 = __float22half2_rn(make_float2(w0, w1));
            __half2 p1 = __float22half2_rn(make_float2(w2, w3));
            pk[q * 2 + 0] = *(uint32_t*)&p0;
            pk[q * 2 + 1] = *(uint32_t*)&p1;
        }
        __half* ab = smA + (c & 1) * (128 * AST3) + r * AST3 + jq;
        *(uint4*)ab       = *(uint4*)&pk[0];
        *(uint4*)(ab + 8) = *(uint4*)&pk[4];
    };

    auto mma_phase = [&](int c) {
        const __half* A = smA + (c & 1) * (128 * AST3);
        const __half* B = smB + (c % 3) * (64 * BST3);
#pragma unroll
        for (int ks = 0; ks < 4; ks++) {
            uint32_t af[2][4];
#pragma unroll
            for (int mi = 0; mi < 2; mi++)
                ldm_x4(af[mi], A + (wi * 32 + mi * 16 + (lid & 15)) * AST3
                               + ks * 16 + (lid >> 4) * 8);
            uint32_t bf4[4][4];
#pragma unroll
            for (int np = 0; np < 4; np++)
                ldm_x4_t(bf4[np], B + (ks * 16 + (lid & 7) + ((lid >> 3) & 1) * 8) * BST3
                                  + wo * 64 + np * 16 + (lid >> 4) * 8);
#pragma unroll
            for (int mi = 0; mi < 2; mi++)
#pragma unroll
                for (int ni = 0; ni < 8; ni++)
                    mma_f16(d[mi][ni], af[mi], &bf4[ni >> 1][(ni & 1) * 2]);
        }
    };

    // ---- pipeline: 2 stages in flight ----
    stage(0); CP_COMMIT();
    stage(1); CP_COMMIT();
    __syncthreads();                 // sEF visible

    for (int c = 0; c < NIT; c++) {
        CP_WAIT1();                  // group c complete (adj self-visible)
        gen_sts(c);                  // reads adj slot c&1 (own segs), writes A[c&1]
        __syncthreads();             // publish A[c&1] + B slot c%3; retire mma(c-1)
        if (c + 2 < NIT) stage(c + 2);
        CP_COMMIT();                 // uniform group numbering
        mma_phase(c);
    }

    den[t] = dn;
    __syncthreads();

    // ---- epilogue ----
#pragma unroll
    for (int mi = 0; mi < 2; mi++) {
        const int r0 = wi * 32 + mi * 16 + g;
        const int r1 = r0 + 8;
        const float inv0 = 1.0f / (den[4 * r0] + den[4 * r0 + 1]
                                 + den[4 * r0 + 2] + den[4 * r0 + 3]);
        const float inv1 = 1.0f / (den[4 * r1] + den[4 * r1 + 1]
                                 + den[4 * r1 + 2] + den[4 * r1 + 3]);
        float* op0 = out + (size_t)(bz * NROW + i0 + r0) * FDIM + wo * 64 + tig * 2;
        float* op1 = out + (size_t)(bz * NROW + i0 + r1) * FDIM + wo * 64 + tig * 2;
#pragma unroll
        for (int ni = 0; ni < 8; ni++) {
            *(float2*)(op0 + ni * 8) = make_float2(d[mi][ni][0] * inv0, d[mi][ni][1] * inv0);
            *(float2*)(op1 + ni * 8) = make_float2(d[mi][ni][2] * inv1, d[mi][ni][3] * inv1);
        }
    }
}

// =====================================================================
extern "C" void kernel_launch(void* const* d_in, const int* in_sizes, int n_in,
                              void* d_out, int out_size)
{
    const float* h   = (const float*)d_in[0];
    const int*   adj = (const int*)  d_in[1];
    const float* W   = (const float*)d_in[2];
    const float* a   = (const float*)d_in[3];
    float* out = (float*)d_out;

    float *Wh, *E1, *F1;
    float2* EFp;
    __half* Whh;
    cudaGetSymbolAddress((void**)&Wh,  g_Wh);
    cudaGetSymbolAddress((void**)&Whh, g_Whh);
    cudaGetSymbolAddress((void**)&E1,  g_E1);
    cudaGetSymbolAddress((void**)&F1,  g_F1);
    cudaGetSymbolAddress((void**)&EFp, g_EF);

    const int smem1 = (2 * 128 * K1ST + 2 * 256 * K1ST) * (int)sizeof(uint32_t); // 110592
    cudaFuncSetAttribute(wh_mma_kernel,   cudaFuncAttributeMaxDynamicSharedMemorySize, smem1);
    cudaFuncSetAttribute(attn_f16_kernel, cudaFuncAttributeMaxDynamicSharedMemorySize, SM3_SZ);

    wh_mma_kernel<<<NTOT / 128, 512, smem1>>>(h, W, Wh, Whh);
    fvec_kernel<<<NTOT / 8, 256>>>(Wh, a, E1, F1, EFp);
    attn_f16_kernel<<<dim3(NROW / 128, NBATCH), 512, SM3_SZ>>>(
        adj, Whh, E1, F1, EFp, out);
}

// round 11
// speedup vs baseline: 1.1534x; 1.1534x over previous
#include <cuda_runtime.h>
#include <cuda_fp16.h>
#include <cstdint>

// GraphAttentionLayer: B=8, N=2048, Fin=Fout=256
//  K1: Wh = h @ W^T  (tf32 mma.sync, 128x256 blocks, single wave)  [R9, 30.4us]
//  K2: per-row E1=exp(f1), F1=exp(.2 f1), EF=(exp(f2), exp(.2 f2))
//  K3: fp16 m16n8k16 attention, 128i x 256o, KJ=32, cp.async 4-deep rings,
//      gen -> sync -> mma (unfused)                                 [R7, ~112us]
//      w_ij = adj ? (E2_j > 1/E1_i ? E1_i*E2_j : F1_i*F2_j) : 0  (exact leaky+exp)

#define NROW   2048
#define FDIM   256
#define NBATCH 8
#define NTOT   (NBATCH * NROW)

#define K1ST 36
#define KJ   32
#define NIT  (NROW / KJ)   // 64

// ---------------- scratch ----------------
__device__ float  g_Wh [NTOT * FDIM];
__device__ __half g_Whh[NTOT * FDIM];
__device__ float  g_E1[NTOT], g_F1[NTOT];
__device__ float2 g_EF[NTOT];

// ---------------- helpers ----------------
__device__ __forceinline__ uint32_t to_tf32(float x) {
    uint32_t r; asm("cvt.rna.tf32.f32 %0, %1;" : "=r"(r) : "f"(x)); return r;
}
__device__ __forceinline__ void mma_tf32(float* d, const uint32_t* a, const uint32_t* b) {
    asm volatile(
        "mma.sync.aligned.m16n8k8.row.col.f32.tf32.tf32.f32 "
        "{%0,%1,%2,%3}, {%4,%5,%6,%7}, {%8,%9}, {%0,%1,%2,%3};"
        : "+f"(d[0]), "+f"(d[1]), "+f"(d[2]), "+f"(d[3])
        : "r"(a[0]), "r"(a[1]), "r"(a[2]), "r"(a[3]), "r"(b[0]), "r"(b[1]));
}
__device__ __forceinline__ void mma_f16(float* d, const uint32_t* a, const uint32_t* b) {
    asm volatile(
        "mma.sync.aligned.m16n8k16.row.col.f32.f16.f16.f32 "
        "{%0,%1,%2,%3}, {%4,%5,%6,%7}, {%8,%9}, {%0,%1,%2,%3};"
        : "+f"(d[0]), "+f"(d[1]), "+f"(d[2]), "+f"(d[3])
        : "r"(a[0]), "r"(a[1]), "r"(a[2]), "r"(a[3]), "r"(b[0]), "r"(b[1]));
}
__device__ __forceinline__ void ldm_x4(uint32_t* r, const void* p) {
    uint32_t a = (uint32_t)__cvta_generic_to_shared(p);
    asm volatile("ldmatrix.sync.aligned.m8n8.x4.shared.b16 {%0,%1,%2,%3}, [%4];"
                 : "=r"(r[0]), "=r"(r[1]), "=r"(r[2]), "=r"(r[3]) : "r"(a));
}
__device__ __forceinline__ void ldm_x4_t(uint32_t* r, const void* p) {
    uint32_t a = (uint32_t)__cvta_generic_to_shared(p);
    asm volatile("ldmatrix.sync.aligned.m8n8.x4.trans.shared.b16 {%0,%1,%2,%3}, [%4];"
                 : "=r"(r[0]), "=r"(r[1]), "=r"(r[2]), "=r"(r[3]) : "r"(a));
}
__device__ __forceinline__ void cp_async16(void* dst, const void* src) {
    uint32_t d = (uint32_t)__cvta_generic_to_shared(dst);
    asm volatile("cp.async.cg.shared.global [%0], [%1], 16;" :: "r"(d), "l"(src));
}
#define CP_COMMIT() asm volatile("cp.async.commit_group;" ::: "memory")
#define CP_WAIT2()  asm volatile("cp.async.wait_group 2;" ::: "memory")

// =====================================================================
// Kernel 1: Wh = h @ W^T, tf32 mma, 128n x 256o blocks, 512 threads.
// =====================================================================
__global__ void __launch_bounds__(512, 1) wh_mma_kernel(
    const float* __restrict__ h, const float* __restrict__ W,
    float* __restrict__ Wh, __half* __restrict__ Whh)
{
    extern __shared__ uint32_t sm1[];
    uint32_t* sA = sm1;                      // [2][128][K1ST]
    uint32_t* sB = sm1 + 2 * 128 * K1ST;     // [2][256][K1ST]

    const int t = threadIdx.x, wid = t >> 5, lid = t & 31;
    const int n0 = blockIdx.x * 128;
    const int rh = t >> 2, sh = (t & 3) * 8;
    const int rw = t >> 1, sw = (t & 1) * 16;
    const int wi = wid & 3, wo = wid >> 2;
    const int g = lid >> 2, tig = lid & 3;

    const float* hp = h + (size_t)(n0 + rh) * FDIM + sh;
    const float* wp = W + (size_t)rw * FDIM + sw;

    float d[2][8][4];
#pragma unroll
    for (int mi = 0; mi < 2; mi++)
#pragma unroll
        for (int ni = 0; ni < 8; ni++)
#pragma unroll
            for (int q = 0; q < 4; q++) d[mi][ni][q] = 0.f;

    float4 hr[2], wr[4];

    auto ldg = [&](int it) {
        const int f0 = it * 32;
        hr[0] = *(const float4*)(hp + f0);
        hr[1] = *(const float4*)(hp + f0 + 4);
#pragma unroll
        for (int q = 0; q < 4; q++)
            wr[q] = *(const float4*)(wp + f0 + q * 4);
    };
    auto sts = [&](int bf) {
        uint32_t* ab = sA + bf * 128 * K1ST + rh * K1ST + sh;
        uint32_t* bb = sB + bf * 256 * K1ST + rw * K1ST + sw;
#pragma unroll
        for (int q = 0; q < 2; q++)
            *(uint4*)(ab + q * 4) = make_uint4(to_tf32(hr[q].x), to_tf32(hr[q].y),
                                               to_tf32(hr[q].z), to_tf32(hr[q].w));
#pragma unroll
        for (int q = 0; q < 4; q++)
            *(uint4*)(bb + q * 4) = make_uint4(to_tf32(wr[q].x), to_tf32(wr[q].y),
                                               to_tf32(wr[q].z), to_tf32(wr[q].w));
    };
    auto mma_phase = [&](int bf) {
        const uint32_t* A = sA + bf * 128 * K1ST;
        const uint32_t* B = sB + bf * 256 * K1ST;
#pragma unroll
        for (int ks = 0; ks < 4; ks++) {
            uint32_t af[2][4];
#pragma unroll
            for (int mi = 0; mi < 2; mi++) {
                const int row = wi * 32 + mi * 16 + g;
                const int kc  = ks * 8 + tig;
                af[mi][0] = A[row * K1ST + kc];
                af[mi][1] = A[(row + 8) * K1ST + kc];
                af[mi][2] = A[row * K1ST + kc + 4];
                af[mi][3] = A[(row + 8) * K1ST + kc + 4];
            }
            uint32_t bfr[8][2];
#pragma unroll
            for (int ni = 0; ni < 8; ni++) {
                const int col = wo * 64 + ni * 8 + g;
                const int kc  = ks * 8 + tig;
                bfr[ni][0] = B[col * K1ST + kc];
                bfr[ni][1] = B[col * K1ST + kc + 4];
            }
#pragma unroll
            for (int mi = 0; mi < 2; mi++)
#pragma unroll
                for (int ni = 0; ni < 8; ni++)
                    mma_tf32(d[mi][ni], af[mi], bfr[ni]);
        }
    };

    ldg(0); sts(0); __syncthreads();
    for (int it = 0; it < 8; it++) {
        if (it + 1 < 8) ldg(it + 1);
        mma_phase(it & 1);
        if (it + 1 < 8) sts((it + 1) & 1);
        __syncthreads();
    }

#pragma unroll
    for (int mi = 0; mi < 2; mi++) {
        const int r0 = wi * 32 + mi * 16 + g;
        const int r1 = r0 + 8;
        float*  o0p = Wh + (size_t)(n0 + r0) * FDIM + wo * 64 + tig * 2;
        float*  o1p = Wh + (size_t)(n0 + r1) * FDIM + wo * 64 + tig * 2;
        __half* h0p = Whh + (size_t)(n0 + r0) * FDIM + wo * 64 + tig * 2;
        __half* h1p = Whh + (size_t)(n0 + r1) * FDIM + wo * 64 + tig * 2;
#pragma unroll
        for (int ni = 0; ni < 8; ni++) {
            *(float2*)(o0p + ni * 8) = make_float2(d[mi][ni][0], d[mi][ni][1]);
            *(float2*)(o1p + ni * 8) = make_float2(d[mi][ni][2], d[mi][ni][3]);
            *(__half2*)(h0p + ni * 8) =
                __float22half2_rn(make_float2(d[mi][ni][0], d[mi][ni][1]));
            *(__half2*)(h1p + ni * 8) =
                __float22half2_rn(make_float2(d[mi][ni][2], d[mi][ni][3]));
        }
    }
}

// =====================================================================
// Kernel 2: per-row f1,f2 -> E1, F1, (E2,F2)
// =====================================================================
__global__ void __launch_bounds__(256) fvec_kernel(
    const float* __restrict__ Wh, const float* __restrict__ a,
    float* __restrict__ E1, float* __restrict__ F1, float2* __restrict__ EF)
{
    const int row  = blockIdx.x * 8 + (threadIdx.x >> 5);
    const int lane = threadIdx.x & 31;
    const float4* wr = (const float4*)(Wh + (size_t)row * FDIM);
    const float4* a1 = (const float4*)a;
    const float4* a2 = (const float4*)(a + FDIM);

    float4 x0 = wr[lane], x1 = wr[lane + 32];
    float4 p0 = a1[lane], p1 = a1[lane + 32];
    float4 q0 = a2[lane], q1 = a2[lane + 32];

    float s1 = x0.x * p0.x + x0.y * p0.y + x0.z * p0.z + x0.w * p0.w
             + x1.x * p1.x + x1.y * p1.y + x1.z * p1.z + x1.w * p1.w;
    float s2 = x0.x * q0.x + x0.y * q0.y + x0.z * q0.z + x0.w * q0.w
             + x1.x * q1.x + x1.y * q1.y + x1.z * q1.z + x1.w * q1.w;
#pragma unroll
    for (int o = 16; o; o >>= 1) {
        s1 += __shfl_xor_sync(0xFFFFFFFFu, s1, o);
        s2 += __shfl_xor_sync(0xFFFFFFFFu, s2, o);
    }
    if (lane == 0) {
        E1[row] = __expf(s1);
        F1[row] = __expf(0.2f * s1);
        EF[row] = make_float2(__expf(s2), __expf(0.2f * s2));
    }
}

// =====================================================================
// Kernel 3: fp16 mma attention, 128i x 256o, 512 threads, KJ=32,
// cp.async 4-deep adj/Whh rings, gen -> sync -> mma (R7 structure).
// =====================================================================
#define AST3 40            // A tile row stride (halves): 32 + 8 pad
#define BST3 264           // B tile k-row stride (halves): 256 + 8 pad
// smem layout (bytes)
#define OFF_A   0          // A: 2 * 128 * 40 halves          = 20480
#define OFF_B   20480      // B ring: 4 * 32 * 264 halves     = 67584
#define OFF_ADJ 88064      // adj ring: 4 * 128 * 32 ints     = 65536
#define OFF_EF  153600     // EF: 2048 * float2               = 16384
#define OFF_DN  169984     // den: 512 * float                =  2048
#define SM3_SZ  172032

__global__ void __launch_bounds__(512, 1) attn_f16_kernel(
    const int*  __restrict__ adj,
    const __half* __restrict__ Whh,
    const float* __restrict__ E1, const float* __restrict__ F1,
    const float2* __restrict__ EF,
    float* __restrict__ out)
{
    extern __shared__ char smc[];
    __half* smA = (__half*)(smc + OFF_A);
    __half* smB = (__half*)(smc + OFF_B);
    char*   smJ = smc + OFF_ADJ;
    float2* sEF = (float2*)(smc + OFF_EF);
    float*  den = (float*)(smc + OFF_DN);

    const int t = threadIdx.x, wid = t >> 5, lid = t & 31;
    const int bz = blockIdx.y, i0 = blockIdx.x * 128;
    const int r  = t >> 2, jq = (t & 3) * 8;     // w-gen: row r, 8 j's
    const int wi = wid & 3, wo = wid >> 2;       // warp tile: rows wi*32, cols wo*64
    const int g  = lid >> 2, tig = lid & 3;

    // ---- stage (E2,F2) once ----
    {
        const float4* src = (const float4*)(EF + bz * NROW);
        float4* dst = (float4*)sEF;
        dst[t]       = src[t];
        dst[t + 512] = src[t + 512];
    }

    const int row_g = bz * NROW + i0 + r;
    const float E1r  = E1[row_g], F1r = F1[row_g];
    const float tinv = __frcp_rn(E1r);           // s>0  <=>  E2_j > 1/E1_i

    // cp.async source bases
    const char* adj_src = (const char*)(adj + (size_t)row_g * NROW) + (t & 3) * 32;
    const char* whh_src = (const char*)(Whh + (size_t)(bz * NROW + (t & 31)) * FDIM)
                          + (t >> 5) * 16;

    auto stage = [&](int c) {
        const int slot = c & 3;
        {
            char* dst = smJ + slot * 16384 + r * 128 + (t & 3) * 32;
            const char* src = adj_src + (size_t)c * 128;
            cp_async16(dst, src);
            cp_async16(dst + 16, src + 16);
        }
        {
            char* dst = (char*)smB + slot * (32 * BST3 * 2)
                        + (t & 31) * (BST3 * 2) + (t >> 5) * 16;
            const char* src = whh_src + (size_t)c * (KJ * FDIM * 2);
            cp_async16(dst, src);
            cp_async16(dst + 256, src + 256);
        }
    };

    float d[2][8][4];
#pragma unroll
    for (int mi = 0; mi < 2; mi++)
#pragma unroll
        for (int ni = 0; ni < 8; ni++)
#pragma unroll
            for (int q = 0; q < 4; q++) d[mi][ni][q] = 0.f;
    float dn = 0.f;

    auto gen = [&](int c) {
        const int slot = c & 3;
        const int4* ap = (const int4*)(smJ + slot * 16384 + r * 128 + jq * 4);
        int4 a0 = ap[0], a1 = ap[1];
        const float2* efp = sEF + c * KJ + jq;
        float w[8];
        const int* am0 = (const int*)&a0;
        const int* am1 = (const int*)&a1;
#pragma unroll
        for (int e = 0; e < 4; e++) {
            const float2 ef = efp[e];
            const float v = am0[e] ? (ef.x > tinv ? E1r * ef.x : F1r * ef.y) : 0.f;
            dn += v; w[e] = v;
        }
#pragma unroll
        for (int e = 0; e < 4; e++) {
            const float2 ef = efp[4 + e];
            const float v = am1[e] ? (ef.x > tinv ? E1r * ef.x : F1r * ef.y) : 0.f;
            dn += v; w[4 + e] = v;
        }
        __half2 p0 = __float22half2_rn(make_float2(w[0], w[1]));
        __half2 p1 = __float22half2_rn(make_float2(w[2], w[3]));
        __half2 p2 = __float22half2_rn(make_float2(w[4], w[5]));
        __half2 p3 = __float22half2_rn(make_float2(w[6], w[7]));
        uint4 pk = make_uint4(*(uint32_t*)&p0, *(uint32_t*)&p1,
                              *(uint32_t*)&p2, *(uint32_t*)&p3);
        *(uint4*)(smA + (c & 1) * (128 * AST3) + r * AST3 + jq) = pk;
    };

    auto mma_phase = [&](int c) {
        const __half* A = smA + (c & 1) * (128 * AST3);
        const __half* B = smB + (c & 3) * (32 * BST3);
#pragma unroll
        for (int ks = 0; ks < 2; ks++) {
            uint32_t af[2][4];
#pragma unroll
            for (int mi = 0; mi < 2; mi++)
                ldm_x4(af[mi], A + (wi * 32 + mi * 16 + (lid & 15)) * AST3
                               + ks * 16 + (lid >> 4) * 8);
            uint32_t bf4[4][4];
#pragma unroll
            for (int np = 0; np < 4; np++)
                ldm_x4_t(bf4[np], B + (ks * 16 + (lid & 7) + ((lid >> 3) & 1) * 8) * BST3
                                  + wo * 64 + np * 16 + (lid >> 4) * 8);
#pragma unroll
            for (int mi = 0; mi < 2; mi++)
#pragma unroll
                for (int ni = 0; ni < 8; ni++)
                    mma_f16(d[mi][ni], af[mi], &bf4[ni >> 1][(ni & 1) * 2]);
        }
    };

    // ---- pipeline ----
    stage(0); CP_COMMIT();
    stage(1); CP_COMMIT();
    stage(2); CP_COMMIT();
    __syncthreads();                 // sEF visible

    for (int c = 0; c < NIT; c++) {
        CP_WAIT2();                  // group c complete (self-visible adj segs)
        gen(c);                      // A[c&1] <- w ; reads adj slot c&3 (own segs)
        __syncthreads();             // A + B slot c visible; mma(c-1) fully done
        if (c + 3 < NIT) stage(c + 3);
        CP_COMMIT();                 // keep group numbering uniform
        mma_phase(c);
    }

    den[t] = dn;
    __syncthreads();

    // ---- epilogue ----
#pragma unroll
    for (int mi = 0; mi < 2; mi++) {
        const int r0 = wi * 32 + mi * 16 + g;
        const int r1 = r0 + 8;
        const float inv0 = 1.0f / (den[4 * r0] + den[4 * r0 + 1]
                                 + den[4 * r0 + 2] + den[4 * r0 + 3]);
        const float inv1 = 1.0f / (den[4 * r1] + den[4 * r1 + 1]
                                 + den[4 * r1 + 2] + den[4 * r1 + 3]);
        float* op0 = out + (size_t)(bz * NROW + i0 + r0) * FDIM + wo * 64 + tig * 2;
        float* op1 = out + (size_t)(bz * NROW + i0 + r1) * FDIM + wo * 64 + tig * 2;
#pragma unroll
        for (int ni = 0; ni < 8; ni++) {
            *(float2*)(op0 + ni * 8) = make_float2(d[mi][ni][0] * inv0, d[mi][ni][1] * inv0);
            *(float2*)(op1 + ni * 8) = make_float2(d[mi][ni][2] * inv1, d[mi][ni][3] * inv1);
        }
    }
}

// =====================================================================
extern "C" void kernel_launch(void* const* d_in, const int* in_sizes, int n_in,
                              void* d_out, int out_size)
{
    const float* h   = (const float*)d_in[0];
    const int*   adj = (const int*)  d_in[1];
    const float* W   = (const float*)d_in[2];
    const float* a   = (const float*)d_in[3];
    float* out = (float*)d_out;

    float *Wh, *E1, *F1;
    float2* EFp;
    __half* Whh;
    cudaGetSymbolAddress((void**)&Wh,  g_Wh);
    cudaGetSymbolAddress((void**)&Whh, g_Whh);
    cudaGetSymbolAddress((void**)&E1,  g_E1);
    cudaGetSymbolAddress((void**)&F1,  g_F1);
    cudaGetSymbolAddress((void**)&EFp, g_EF);

    const int smem1 = (2 * 128 * K1ST + 2 * 256 * K1ST) * (int)sizeof(uint32_t); // 110592
    cudaFuncSetAttribute(wh_mma_kernel,   cudaFuncAttributeMaxDynamicSharedMemorySize, smem1);
    cudaFuncSetAttribute(attn_f16_kernel, cudaFuncAttributeMaxDynamicSharedMemorySize, SM3_SZ);

    wh_mma_kernel<<<NTOT / 128, 512, smem1>>>(h, W, Wh, Whh);
    fvec_kernel<<<NTOT / 8, 256>>>(Wh, a, E1, F1, EFp);
    attn_f16_kernel<<<dim3(NROW / 128, NBATCH), 512, SM3_SZ>>>(
        adj, Whh, E1, F1, EFp, out);
}